// round 14
// baseline (speedup 1.0000x reference)
#include <cuda_runtime.h>
#include <cuda_fp16.h>
#include <math.h>
#include <stdint.h>

#define CB   4
#define CS   2048
#define CD   1024
#define CH   16
#define CDH  64
#define MROWS (CB*CS)
#define LN_EPS 1e-5f

// ---------------- scratch ----------------
__device__ float  g_chunk[(size_t)MROWS*CD];          // f32 for LN
__device__ float  g_proj [(size_t)MROWS*CD];          // f32 for LN
__device__ __half g_emb_h  [(size_t)MROWS*CD];
__device__ __half g_chunk_h[(size_t)MROWS*CD];
__device__ __half g_qkv_h  [(size_t)MROWS*3*CD];
__device__ __half g_attn_h [(size_t)MROWS*CD];
__device__ __half g_cw_h[(size_t)CD*2*CD];
__device__ __half g_iw_h[(size_t)3*CD*CD];
__device__ __half g_ow_h[(size_t)CD*CD];

// ---------------- helpers ----------------
__device__ __forceinline__ float ex2f(float x) {
    float y; asm("ex2.approx.f32 %0, %1;" : "=f"(y) : "f"(x)); return y;
}
__device__ __forceinline__ uint32_t pack_f16(float lo, float hi) {
    uint32_t r; asm("cvt.rn.f16x2.f32 %0, %1, %2;" : "=r"(r) : "f"(hi), "f"(lo));
    return r;
}
__device__ __forceinline__ void mma_f16(float c[4], const uint32_t a[4],
                                        const uint32_t b[2]) {
    asm volatile(
        "mma.sync.aligned.m16n8k16.row.col.f32.f16.f16.f32 "
        "{%0,%1,%2,%3}, {%4,%5,%6,%7}, {%8,%9}, {%0,%1,%2,%3};\n"
        : "+f"(c[0]), "+f"(c[1]), "+f"(c[2]), "+f"(c[3])
        : "r"(a[0]), "r"(a[1]), "r"(a[2]), "r"(a[3]), "r"(b[0]), "r"(b[1]));
}
__device__ __forceinline__ void ldsm_x4(uint32_t& r0, uint32_t& r1,
                                        uint32_t& r2, uint32_t& r3,
                                        uint32_t addr) {
    asm volatile("ldmatrix.sync.aligned.m8n8.x4.shared.b16 {%0,%1,%2,%3}, [%4];\n"
                 : "=r"(r0), "=r"(r1), "=r"(r2), "=r"(r3) : "r"(addr));
}
__device__ __forceinline__ void ldsm_x4_t(uint32_t& r0, uint32_t& r1,
                                          uint32_t& r2, uint32_t& r3,
                                          uint32_t addr) {
    asm volatile("ldmatrix.sync.aligned.m8n8.x4.trans.shared.b16 {%0,%1,%2,%3}, [%4];\n"
                 : "=r"(r0), "=r"(r1), "=r"(r2), "=r"(r3) : "r"(addr));
}
__device__ __forceinline__ uint32_t smem_u32(const void* p) {
    return (uint32_t)__cvta_generic_to_shared(p);
}
__device__ __forceinline__ void cp16(uint32_t dst, const void* src) {
    asm volatile("cp.async.cg.shared.global [%0], [%1], 16;\n"
                 :: "r"(dst), "l"(src));
}
__device__ __forceinline__ void cp16z(uint32_t dst, const void* src, int srcsz) {
    asm volatile("cp.async.cg.shared.global [%0], [%1], 16, %2;\n"
                 :: "r"(dst), "l"(src), "r"(srcsz));
}
__device__ __forceinline__ void cp_commit() {
    asm volatile("cp.async.commit_group;\n");
}
template<int N> __device__ __forceinline__ void cp_wait() {
    asm volatile("cp.async.wait_group %0;\n" :: "n"(N));
}

// ---------------------------------------------------------------------------
// fused f32 -> f16 convert for all 4 tensors (8 elems/thread)
// ---------------------------------------------------------------------------
__global__ __launch_bounds__(256)
void f2h4(const float* __restrict__ s0, __half* __restrict__ d0, int n0,
          const float* __restrict__ s1, __half* __restrict__ d1, int n1,
          const float* __restrict__ s2, __half* __restrict__ d2, int n2,
          const float* __restrict__ s3, __half* __restrict__ d3, int n3) {
    int i = blockIdx.x * 256 + threadIdx.x;
    const float* s; __half* d; int j = i;
    if (j < n0)                { s = s0; d = d0; }
    else if ((j -= n0) < n1)   { s = s1; d = d1; }
    else if ((j -= n1) < n2)   { s = s2; d = d2; }
    else if ((j -= n2) < n3)   { s = s3; d = d3; }
    else return;
    float4 a = ((const float4*)s)[2 * j];
    float4 b = ((const float4*)s)[2 * j + 1];
    uint4 o;
    o.x = pack_f16(a.x, a.y); o.y = pack_f16(a.z, a.w);
    o.z = pack_f16(b.x, b.y); o.w = pack_f16(b.z, b.w);
    ((uint4*)d)[j] = o;
}

// ---------------------------------------------------------------------------
// FP16 NT GEMM (unchanged from R13): 128x128x64 tile, 128 threads, 64x64
// warp tile, 3-stage cp.async ring, LDSM fragments.
// ---------------------------------------------------------------------------
#define GSTGH (128 * 72)                 // halves per stage per matrix
#define GH_SMEM (3 * 2 * GSTGH * 2)      // 110592 B

template<bool WINDOW>
__global__ __launch_bounds__(128, 2)
void gemm_f16(const __half* __restrict__ A, const __half* __restrict__ B,
              const float* __restrict__ bias,
              float* __restrict__ Cf, __half* __restrict__ Ch,
              int M, int N, int K) {
    extern __shared__ __half smh[];
    __half* As = smh;                 // [3][128][72]
    __half* Bs = smh + 3 * GSTGH;     // [3][128][72]

    int tid = threadIdx.x;
    int bm = blockIdx.y * 128, bn = blockIdx.x * 128;
    int warp = tid >> 5, lane = tid & 31, gid = lane >> 2, tig = lane & 3;
    int l7 = lane & 7, l3 = lane >> 3;
    int wm = (warp >> 1) * 64, wn = (warp & 1) * 64;

    float acc[4][8][4];
#pragma unroll
    for (int i = 0; i < 4; i++)
#pragma unroll
        for (int j = 0; j < 8; j++)
#pragma unroll
            for (int c = 0; c < 4; c++) acc[i][j][c] = 0.f;

    auto load_stage = [&](int st, int k0) {
#pragma unroll
        for (int p = 0; p < 8; p++) {
            int id  = tid + p * 128;        // 0..1023
            int row = id >> 3;              // 0..127
            int kq  = (id & 7) << 3;        // 0..56 halves
            uint32_t da = smem_u32(&As[st * GSTGH + row * 72 + kq]);
            if (WINDOW) {
                int m = bm + row;
                int bidx = m >> 11, s = m & (CS - 1);
                int f = k0 + kq, kk = f >> 10, j = f & (CD - 1);
                const __half* src = A + (((size_t)bidx * CS + s + kk) << 10) + j;
                cp16z(da, src, (s + kk < CS) ? 16 : 0);
            } else {
                cp16(da, A + (size_t)(bm + row) * K + k0 + kq);
            }
            cp16(smem_u32(&Bs[st * GSTGH + row * 72 + kq]),
                 B + (size_t)(bn + row) * K + k0 + kq);
        }
        cp_commit();
    };

    int nk = K >> 6;   // BK=64
    load_stage(0, 0);
    load_stage(1, 64);

    int st = 0, pfst = 2;
    for (int kc = 0; kc < nk; kc++) {
        cp_wait<1>();
        __syncthreads();

        int pf = kc + 2;
        if (pf < nk) load_stage(pfst, pf << 6);
        else cp_commit();

        uint32_t Abase = smem_u32(As + st * GSTGH);
        uint32_t Bbase = smem_u32(Bs + st * GSTGH);
#pragma unroll
        for (int g = 0; g < 64; g += 16) {
            uint32_t a[4][4], bf[8][2];
#pragma unroll
            for (int ti = 0; ti < 4; ti++) {
                uint32_t adr = Abase +
                    ((wm + ti * 16 + (l3 & 1) * 8 + l7) * 72 +
                     g + (l3 >> 1) * 8) * 2;
                ldsm_x4(a[ti][0], a[ti][1], a[ti][2], a[ti][3], adr);
            }
#pragma unroll
            for (int tp = 0; tp < 4; tp++) {
                uint32_t adr = Bbase +
                    ((wn + tp * 16 + (l3 & 1) * 8 + l7) * 72 +
                     g + (l3 >> 1) * 8) * 2;
                uint32_t r0, r1, r2, r3;
                ldsm_x4(r0, r1, r2, r3, adr);
                bf[2 * tp][0] = r0; bf[2 * tp][1] = r2;
                bf[2 * tp + 1][0] = r1; bf[2 * tp + 1][1] = r3;
            }
#pragma unroll
            for (int ti = 0; ti < 4; ti++)
#pragma unroll
                for (int tj = 0; tj < 8; tj++)
                    mma_f16(acc[ti][tj], a[ti], bf[tj]);
        }

        st   = (st   == 2) ? 0 : st + 1;
        pfst = (pfst == 2) ? 0 : pfst + 1;
    }

#pragma unroll
    for (int ti = 0; ti < 4; ti++) {
#pragma unroll
        for (int hh = 0; hh < 2; hh++) {
            int row = bm + wm + ti * 16 + gid + 8 * hh;
#pragma unroll
            for (int tj = 0; tj < 8; tj++) {
                int col = bn + wn + tj * 8 + 2 * tig;
                float ox = acc[ti][tj][2 * hh + 0] + bias[col + 0];
                float oy = acc[ti][tj][2 * hh + 1] + bias[col + 1];
                if (Cf) *(float2*)&Cf[(size_t)row * N + col] = make_float2(ox, oy);
                if (Ch) *(uint32_t*)&Ch[(size_t)row * N + col] = pack_f16(ox, oy);
            }
        }
    }
}

// ---------------------------------------------------------------------------
// FP16 flash attention, mi=2: 8 warps x 32 q-rows = 256-row q-tile,
// 256 thr, 1 CTA/SM. K/V fragments loaded once per warp feed BOTH mi
// sub-tiles (halves crossbar traffic per q-row). kv tiles of 128
// (two 64-row halves), 2-stage ring.
// ---------------------------------------------------------------------------
#define FKV (128 * 72)                      // halves per stage per matrix
#define FA_SMEM (2 * 2 * FKV * 2)           // 73728 B

__global__ __launch_bounds__(256, 1)
void flash_f16(const __half* __restrict__ qkv, __half* __restrict__ out) {
    extern __shared__ __half smh[];
    __half* Ks = smh;                 // [2][128][72]
    __half* Vs = smh + 2 * FKV;       // [2][128][72]

    int b = blockIdx.y >> 4, h = blockIdx.y & 15;
    int q0 = blockIdx.x << 8;         // 256-row q tiles
    int tid = threadIdx.x, warp = tid >> 5, lane = tid & 31;
    int gid = lane >> 2, tig = lane & 3;
    int wq = warp * 32;
    int l7 = lane & 7, l3 = lane >> 3;

    const size_t rstr = 3 * CD;
    const __half* qb = qkv + (size_t)b * CS * rstr + h * CDH;
    const __half* kb = qb + CD;
    const __half* vb = qb + 2 * CD;
    const float qscale = 1.4426950408889634f * 0.125f;   // log2e / sqrt(dh)

    // ---- stage Q in two 128-row passes through kv-stage 0
    uint32_t qf[2][4][4];
#pragma unroll
    for (int pass = 0; pass < 2; pass++) {
#pragma unroll
        for (int p = 0; p < 4; p++) {
            int id  = tid + p * 256;    // 0..1023
            int row = id >> 3;          // 0..127
            int c8  = (id & 7) << 3;    // 0..56
            cp16(smem_u32(&Ks[row * 72 + c8]),
                 qb + (size_t)(q0 + pass * 128 + row) * rstr + c8);
        }
        cp_commit();
        cp_wait<0>();
        __syncthreads();
        if ((warp >> 2) == pass) {
            int lb = (warp & 3) * 32;   // local row base within this pass
            uint32_t Qbase = smem_u32(Ks);
#pragma unroll
            for (int mi = 0; mi < 2; mi++)
#pragma unroll
                for (int g4 = 0; g4 < 4; g4++) {
                    uint32_t adr = Qbase +
                        ((lb + mi * 16 + (l3 & 1) * 8 + l7) * 72 +
                         g4 * 16 + (l3 >> 1) * 8) * 2;
                    ldsm_x4(qf[mi][g4][0], qf[mi][g4][1],
                            qf[mi][g4][2], qf[mi][g4][3], adr);
                }
        }
        __syncthreads();
    }

    auto load_kv = [&](int st, int kt) {
#pragma unroll
        for (int p = 0; p < 4; p++) {
            int id  = tid + p * 256;    // 0..1023
            int row = id >> 3;          // 0..127
            int c8  = (id & 7) << 3;
            cp16(smem_u32(&Ks[st * FKV + row * 72 + c8]),
                 kb + (size_t)(kt + row) * rstr + c8);
            cp16(smem_u32(&Vs[st * FKV + row * 72 + c8]),
                 vb + (size_t)(kt + row) * rstr + c8);
        }
        cp_commit();
    };

    load_kv(0, 0);
    load_kv(1, 128);

    float o[2][9][4];
#pragma unroll
    for (int mi = 0; mi < 2; mi++)
#pragma unroll
        for (int n = 0; n < 9; n++)
#pragma unroll
            for (int c = 0; c < 4; c++) o[mi][n][c] = 0.f;

    const uint32_t bones = (gid == 0) ? 0x3C003C00u : 0u;   // fp16 {1,1}
    const int nkt = CS / 128;   // 16

    for (int it = 0; it < nkt; it++) {
        int st = it & 1;
        cp_wait<1>();
        __syncthreads();

#pragma unroll
        for (int half = 0; half < 2; half++) {
            uint32_t Kbase = smem_u32(Ks + st * FKV + half * 64 * 72);
            uint32_t Vbase = smem_u32(Vs + st * FKV + half * 64 * 72);

            // S = Q @ K^T : K fragments shared across both mi
            float sc[2][8][4];
#pragma unroll
            for (int mi = 0; mi < 2; mi++)
#pragma unroll
                for (int n = 0; n < 8; n++)
#pragma unroll
                    for (int c = 0; c < 4; c++) sc[mi][n][c] = 0.f;
#pragma unroll
            for (int g4 = 0; g4 < 4; g4++) {
#pragma unroll
                for (int np = 0; np < 4; np++) {
                    uint32_t adr = Kbase +
                        ((np * 16 + (l3 & 1) * 8 + l7) * 72 +
                         g4 * 16 + (l3 >> 1) * 8) * 2;
                    uint32_t r0, r1, r2, r3;
                    ldsm_x4(r0, r1, r2, r3, adr);
                    uint32_t b0[2] = {r0, r2};
                    uint32_t b1[2] = {r1, r3};
                    mma_f16(sc[0][2 * np],     qf[0][g4], b0);
                    mma_f16(sc[0][2 * np + 1], qf[0][g4], b1);
                    mma_f16(sc[1][2 * np],     qf[1][g4], b0);
                    mma_f16(sc[1][2 * np + 1], qf[1][g4], b1);
                }
            }

            // P = exp2(S * qscale) into fp16 A-fragments
            uint32_t pf[2][4][4];
#pragma unroll
            for (int mi = 0; mi < 2; mi++)
#pragma unroll
                for (int n = 0; n < 8; n++) {
                    int t = n >> 1, hi = (n & 1) << 1;
                    pf[mi][t][hi + 0] = pack_f16(ex2f(sc[mi][n][0] * qscale),
                                                 ex2f(sc[mi][n][1] * qscale));
                    pf[mi][t][hi + 1] = pack_f16(ex2f(sc[mi][n][2] * qscale),
                                                 ex2f(sc[mi][n][3] * qscale));
                }

            // O += P @ V : V fragments shared across both mi
#pragma unroll
            for (int t = 0; t < 4; t++) {
#pragma unroll
                for (int a = 0; a < 4; a++) {
                    uint32_t adr = Vbase +
                        (16 * t + (l3 & 1) * 8 + l7) * 144 +
                        (2 * a + (l3 >> 1)) * 16;
                    uint32_t v0, v1, v2, v3;
                    ldsm_x4_t(v0, v1, v2, v3, adr);
                    uint32_t bv0[2] = {v0, v1};
                    uint32_t bv1[2] = {v2, v3};
                    mma_f16(o[0][2 * a],     pf[0][t], bv0);
                    mma_f16(o[0][2 * a + 1], pf[0][t], bv1);
                    mma_f16(o[1][2 * a],     pf[1][t], bv0);
                    mma_f16(o[1][2 * a + 1], pf[1][t], bv1);
                }
                {
                    uint32_t bv[2] = {bones, bones};
                    mma_f16(o[0][8], pf[0][t], bv);
                    mma_f16(o[1][8], pf[1][t], bv);
                }
            }
        }

        __syncthreads();
        if (it + 2 < nkt) load_kv(st, (it + 2) * 128);
        else cp_commit();
    }

    // normalize + write fp16 (row sums in tig==0 lanes of o[mi][8])
    int base = lane & 28;
#pragma unroll
    for (int mi = 0; mi < 2; mi++)
#pragma unroll
        for (int hh = 0; hh < 2; hh++) {
            float lsv = __shfl_sync(0xffffffffu, o[mi][8][hh ? 2 : 0], base);
            float inv = 1.f / lsv;
            int row = q0 + wq + mi * 16 + gid + 8 * hh;
#pragma unroll
            for (int n = 0; n < 8; n++) {
                int col = h * CDH + n * 8 + 2 * tig;
                *(uint32_t*)&out[((size_t)b * CS + row) * CD + col] =
                    pack_f16(o[mi][n][2 * hh] * inv, o[mi][n][2 * hh + 1] * inv);
            }
        }
}

// ---------------------------------------------------------------------------
// Fused residual add + LayerNorm
// ---------------------------------------------------------------------------
__global__ __launch_bounds__(256)
void add_ln(const float* __restrict__ chunk, const float* __restrict__ proj,
            const float* __restrict__ g, const float* __restrict__ beta,
            float* __restrict__ out) {
    int row = blockIdx.x;
    int tid = threadIdx.x;
    size_t base = (size_t)row * CD + tid * 4;

    float4 c = *(const float4*)&chunk[base];
    float4 p = *(const float4*)&proj[base];
    float4 x = make_float4(c.x + p.x, c.y + p.y, c.z + p.z, c.w + p.w);

    float s  = x.x + x.y + x.z + x.w;
    float s2 = x.x * x.x + x.y * x.y + x.z * x.z + x.w * x.w;
#pragma unroll
    for (int off = 16; off; off >>= 1) {
        s  += __shfl_xor_sync(0xffffffffu, s,  off);
        s2 += __shfl_xor_sync(0xffffffffu, s2, off);
    }
    __shared__ float rs[8], rs2[8];
    __shared__ float s_mu, s_rstd;
    int lane = tid & 31, warp = tid >> 5;
    if (lane == 0) { rs[warp] = s; rs2[warp] = s2; }
    __syncthreads();
    if (tid == 0) {
        float a = 0.f, b2 = 0.f;
#pragma unroll
        for (int w = 0; w < 8; w++) { a += rs[w]; b2 += rs2[w]; }
        float mean = a * (1.f / CD);
        float var  = b2 * (1.f / CD) - mean * mean;
        s_mu = mean;
        s_rstd = rsqrtf(var + LN_EPS);
    }
    __syncthreads();
    float mu = s_mu, rstd = s_rstd;

    float4 gv = *(const float4*)&g[tid * 4];
    float4 bv = *(const float4*)&beta[tid * 4];
    float4 y;
    y.x = (x.x - mu) * rstd * gv.x + bv.x;
    y.y = (x.y - mu) * rstd * gv.y + bv.y;
    y.z = (x.z - mu) * rstd * gv.z + bv.z;
    y.w = (x.w - mu) * rstd * gv.w + bv.w;
    *(float4*)&out[base] = y;
}

// ---------------------------------------------------------------------------
extern "C" void kernel_launch(void* const* d_in, const int* in_sizes, int n_in,
                              void* d_out, int out_size) {
    const float* emb     = (const float*)d_in[0];
    const float* chunk_w = (const float*)d_in[1];
    const float* chunk_b = (const float*)d_in[2];
    const float* in_w    = (const float*)d_in[3];
    const float* in_b    = (const float*)d_in[4];
    const float* out_w   = (const float*)d_in[5];
    const float* out_b   = (const float*)d_in[6];
    const float* ln_g    = (const float*)d_in[7];
    const float* ln_b    = (const float*)d_in[8];
    float* out = (float*)d_out;

    float *chunk, *proj;
    __half *emb_h, *chunk_h, *qkv_h, *attn_h, *cw_h, *iw_h, *ow_h;
    cudaGetSymbolAddress((void**)&chunk,   g_chunk);
    cudaGetSymbolAddress((void**)&proj,    g_proj);
    cudaGetSymbolAddress((void**)&emb_h,   g_emb_h);
    cudaGetSymbolAddress((void**)&chunk_h, g_chunk_h);
    cudaGetSymbolAddress((void**)&qkv_h,   g_qkv_h);
    cudaGetSymbolAddress((void**)&attn_h,  g_attn_h);
    cudaGetSymbolAddress((void**)&cw_h,    g_cw_h);
    cudaGetSymbolAddress((void**)&iw_h,    g_iw_h);
    cudaGetSymbolAddress((void**)&ow_h,    g_ow_h);

    cudaFuncSetAttribute(gemm_f16<true>,
                         cudaFuncAttributeMaxDynamicSharedMemorySize, GH_SMEM);
    cudaFuncSetAttribute(gemm_f16<false>,
                         cudaFuncAttributeMaxDynamicSharedMemorySize, GH_SMEM);
    cudaFuncSetAttribute(flash_f16,
                         cudaFuncAttributeMaxDynamicSharedMemorySize, FA_SMEM);

    // 0) fused f32 -> f16 conversions
    {
        int n0 = MROWS * CD / 8;
        int n1 = CD * 2 * CD / 8;
        int n2 = 3 * CD * CD / 8;
        int n3 = CD * CD / 8;
        int nt = n0 + n1 + n2 + n3;
        f2h4<<<(nt + 255) / 256, 256>>>(emb, emb_h, n0, chunk_w, cw_h, n1,
                                        in_w, iw_h, n2, out_w, ow_h, n3);
    }
    // 1) chunk = windows @ chunk_w^T + chunk_b  (f32 + f16 outputs)
    {
        dim3 grid(CD / 128, MROWS / 128);
        gemm_f16<true><<<grid, 128, GH_SMEM>>>(emb_h, cw_h, chunk_b,
                                               chunk, chunk_h,
                                               MROWS, CD, 2 * CD);
    }
    // 2) qkv = chunk @ in_proj_w^T + in_proj_b  (f16 output only)
    {
        dim3 grid(3 * CD / 128, MROWS / 128);
        gemm_f16<false><<<grid, 128, GH_SMEM>>>(chunk_h, iw_h, in_b,
                                                nullptr, qkv_h,
                                                MROWS, 3 * CD, CD);
    }
    // 3) flash attention (fp16 in/out, 256-row q tiles)
    {
        dim3 grid(CS / 256, CB * CH);
        flash_f16<<<grid, 256, FA_SMEM>>>(qkv_h, attn_h);
    }
    // 4) proj = attn @ out_proj_w^T + out_proj_b  (f32 output only)
    {
        dim3 grid(CD / 128, MROWS / 128);
        gemm_f16<false><<<grid, 128, GH_SMEM>>>(attn_h, ow_h, out_b,
                                                proj, nullptr,
                                                MROWS, CD, CD);
    }
    // 5) out = LayerNorm(chunk + proj)
    add_ln<<<MROWS, 256>>>(chunk, proj, ln_g, ln_b, out);
}

// round 15
// speedup vs baseline: 1.0532x; 1.0532x over previous
#include <cuda_runtime.h>
#include <cuda_fp16.h>
#include <math.h>
#include <stdint.h>

#define CB   4
#define CS   2048
#define CD   1024
#define CH   16
#define CDH  64
#define MROWS (CB*CS)
#define LN_EPS 1e-5f

// ---------------- scratch ----------------
__device__ float  g_chunk[(size_t)MROWS*CD];          // f32 for LN
__device__ float  g_proj [(size_t)MROWS*CD];          // f32 for LN
__device__ __half g_emb_h  [(size_t)MROWS*CD];
__device__ __half g_chunk_h[(size_t)MROWS*CD];
__device__ __half g_qkv_h  [(size_t)MROWS*3*CD];
__device__ __half g_attn_h [(size_t)MROWS*CD];
__device__ __half g_cw_h[(size_t)CD*2*CD];
__device__ __half g_iw_h[(size_t)3*CD*CD];
__device__ __half g_ow_h[(size_t)CD*CD];

// ---------------- helpers ----------------
__device__ __forceinline__ float ex2f(float x) {
    float y; asm("ex2.approx.f32 %0, %1;" : "=f"(y) : "f"(x)); return y;
}
__device__ __forceinline__ uint32_t pack_f16(float lo, float hi) {
    uint32_t r; asm("cvt.rn.f16x2.f32 %0, %1, %2;" : "=r"(r) : "f"(hi), "f"(lo));
    return r;
}
__device__ __forceinline__ void mma_f16(float c[4], const uint32_t a[4],
                                        const uint32_t b[2]) {
    asm volatile(
        "mma.sync.aligned.m16n8k16.row.col.f32.f16.f16.f32 "
        "{%0,%1,%2,%3}, {%4,%5,%6,%7}, {%8,%9}, {%0,%1,%2,%3};\n"
        : "+f"(c[0]), "+f"(c[1]), "+f"(c[2]), "+f"(c[3])
        : "r"(a[0]), "r"(a[1]), "r"(a[2]), "r"(a[3]), "r"(b[0]), "r"(b[1]));
}
__device__ __forceinline__ void ldsm_x4(uint32_t& r0, uint32_t& r1,
                                        uint32_t& r2, uint32_t& r3,
                                        uint32_t addr) {
    asm volatile("ldmatrix.sync.aligned.m8n8.x4.shared.b16 {%0,%1,%2,%3}, [%4];\n"
                 : "=r"(r0), "=r"(r1), "=r"(r2), "=r"(r3) : "r"(addr));
}
__device__ __forceinline__ void ldsm_x4_t(uint32_t& r0, uint32_t& r1,
                                          uint32_t& r2, uint32_t& r3,
                                          uint32_t addr) {
    asm volatile("ldmatrix.sync.aligned.m8n8.x4.trans.shared.b16 {%0,%1,%2,%3}, [%4];\n"
                 : "=r"(r0), "=r"(r1), "=r"(r2), "=r"(r3) : "r"(addr));
}
__device__ __forceinline__ uint32_t smem_u32(const void* p) {
    return (uint32_t)__cvta_generic_to_shared(p);
}
__device__ __forceinline__ void cp16(uint32_t dst, const void* src) {
    asm volatile("cp.async.cg.shared.global [%0], [%1], 16;\n"
                 :: "r"(dst), "l"(src));
}
__device__ __forceinline__ void cp16z(uint32_t dst, const void* src, int srcsz) {
    asm volatile("cp.async.cg.shared.global [%0], [%1], 16, %2;\n"
                 :: "r"(dst), "l"(src), "r"(srcsz));
}
__device__ __forceinline__ void cp_commit() {
    asm volatile("cp.async.commit_group;\n");
}
template<int N> __device__ __forceinline__ void cp_wait() {
    asm volatile("cp.async.wait_group %0;\n" :: "n"(N));
}

// ---------------------------------------------------------------------------
// fused f32 -> f16 convert for all 4 tensors (8 elems/thread)
// ---------------------------------------------------------------------------
__global__ __launch_bounds__(256)
void f2h4(const float* __restrict__ s0, __half* __restrict__ d0, int n0,
          const float* __restrict__ s1, __half* __restrict__ d1, int n1,
          const float* __restrict__ s2, __half* __restrict__ d2, int n2,
          const float* __restrict__ s3, __half* __restrict__ d3, int n3) {
    int i = blockIdx.x * 256 + threadIdx.x;
    const float* s; __half* d; int j = i;
    if (j < n0)                { s = s0; d = d0; }
    else if ((j -= n0) < n1)   { s = s1; d = d1; }
    else if ((j -= n1) < n2)   { s = s2; d = d2; }
    else if ((j -= n2) < n3)   { s = s3; d = d3; }
    else return;
    float4 a = ((const float4*)s)[2 * j];
    float4 b = ((const float4*)s)[2 * j + 1];
    uint4 o;
    o.x = pack_f16(a.x, a.y); o.y = pack_f16(a.z, a.w);
    o.z = pack_f16(b.x, b.y); o.w = pack_f16(b.z, b.w);
    ((uint4*)d)[j] = o;
}

// ---------------------------------------------------------------------------
// FP16 NT GEMM (unchanged from R13): 128x128x64 tile, 128 threads, 64x64
// warp tile, 3-stage cp.async ring, LDSM fragments.
// ---------------------------------------------------------------------------
#define GSTGH (128 * 72)                 // halves per stage per matrix
#define GH_SMEM (3 * 2 * GSTGH * 2)      // 110592 B

template<bool WINDOW>
__global__ __launch_bounds__(128, 2)
void gemm_f16(const __half* __restrict__ A, const __half* __restrict__ B,
              const float* __restrict__ bias,
              float* __restrict__ Cf, __half* __restrict__ Ch,
              int M, int N, int K) {
    extern __shared__ __half smh[];
    __half* As = smh;                 // [3][128][72]
    __half* Bs = smh + 3 * GSTGH;     // [3][128][72]

    int tid = threadIdx.x;
    int bm = blockIdx.y * 128, bn = blockIdx.x * 128;
    int warp = tid >> 5, lane = tid & 31, gid = lane >> 2, tig = lane & 3;
    int l7 = lane & 7, l3 = lane >> 3;
    int wm = (warp >> 1) * 64, wn = (warp & 1) * 64;

    float acc[4][8][4];
#pragma unroll
    for (int i = 0; i < 4; i++)
#pragma unroll
        for (int j = 0; j < 8; j++)
#pragma unroll
            for (int c = 0; c < 4; c++) acc[i][j][c] = 0.f;

    auto load_stage = [&](int st, int k0) {
#pragma unroll
        for (int p = 0; p < 8; p++) {
            int id  = tid + p * 128;        // 0..1023
            int row = id >> 3;              // 0..127
            int kq  = (id & 7) << 3;        // 0..56 halves
            uint32_t da = smem_u32(&As[st * GSTGH + row * 72 + kq]);
            if (WINDOW) {
                int m = bm + row;
                int bidx = m >> 11, s = m & (CS - 1);
                int f = k0 + kq, kk = f >> 10, j = f & (CD - 1);
                const __half* src = A + (((size_t)bidx * CS + s + kk) << 10) + j;
                cp16z(da, src, (s + kk < CS) ? 16 : 0);
            } else {
                cp16(da, A + (size_t)(bm + row) * K + k0 + kq);
            }
            cp16(smem_u32(&Bs[st * GSTGH + row * 72 + kq]),
                 B + (size_t)(bn + row) * K + k0 + kq);
        }
        cp_commit();
    };

    int nk = K >> 6;   // BK=64
    load_stage(0, 0);
    load_stage(1, 64);

    int st = 0, pfst = 2;
    for (int kc = 0; kc < nk; kc++) {
        cp_wait<1>();
        __syncthreads();

        int pf = kc + 2;
        if (pf < nk) load_stage(pfst, pf << 6);
        else cp_commit();

        uint32_t Abase = smem_u32(As + st * GSTGH);
        uint32_t Bbase = smem_u32(Bs + st * GSTGH);
#pragma unroll
        for (int g = 0; g < 64; g += 16) {
            uint32_t a[4][4], bf[8][2];
#pragma unroll
            for (int ti = 0; ti < 4; ti++) {
                uint32_t adr = Abase +
                    ((wm + ti * 16 + (l3 & 1) * 8 + l7) * 72 +
                     g + (l3 >> 1) * 8) * 2;
                ldsm_x4(a[ti][0], a[ti][1], a[ti][2], a[ti][3], adr);
            }
#pragma unroll
            for (int tp = 0; tp < 4; tp++) {
                uint32_t adr = Bbase +
                    ((wn + tp * 16 + (l3 & 1) * 8 + l7) * 72 +
                     g + (l3 >> 1) * 8) * 2;
                uint32_t r0, r1, r2, r3;
                ldsm_x4(r0, r1, r2, r3, adr);
                bf[2 * tp][0] = r0; bf[2 * tp][1] = r2;
                bf[2 * tp + 1][0] = r1; bf[2 * tp + 1][1] = r3;
            }
#pragma unroll
            for (int ti = 0; ti < 4; ti++)
#pragma unroll
                for (int tj = 0; tj < 8; tj++)
                    mma_f16(acc[ti][tj], a[ti], bf[tj]);
        }

        st   = (st   == 2) ? 0 : st + 1;
        pfst = (pfst == 2) ? 0 : pfst + 1;
    }

#pragma unroll
    for (int ti = 0; ti < 4; ti++) {
#pragma unroll
        for (int hh = 0; hh < 2; hh++) {
            int row = bm + wm + ti * 16 + gid + 8 * hh;
#pragma unroll
            for (int tj = 0; tj < 8; tj++) {
                int col = bn + wn + tj * 8 + 2 * tig;
                float ox = acc[ti][tj][2 * hh + 0] + bias[col + 0];
                float oy = acc[ti][tj][2 * hh + 1] + bias[col + 1];
                if (Cf) *(float2*)&Cf[(size_t)row * N + col] = make_float2(ox, oy);
                if (Ch) *(uint32_t*)&Ch[(size_t)row * N + col] = pack_f16(ox, oy);
            }
        }
    }
}

// ---------------------------------------------------------------------------
// FP16 flash attention, mi=2, 4 warps x 32 q-rows = 128-row q-tile,
// 128 thr, 2 CTAs/SM (two independent barrier domains per SM).
// K/V fragments loaded once per warp feed BOTH mi sub-tiles.
// kv tiles of 128 (two 64-row halves), 2-stage ring.
// ---------------------------------------------------------------------------
#define FKV (128 * 72)                      // halves per stage per matrix
#define FA_SMEM (2 * 2 * FKV * 2)           // 73728 B

__global__ __launch_bounds__(128, 2)
void flash_f16(const __half* __restrict__ qkv, __half* __restrict__ out) {
    extern __shared__ __half smh[];
    __half* Ks = smh;                 // [2][128][72]
    __half* Vs = smh + 2 * FKV;       // [2][128][72]

    int b = blockIdx.y >> 4, h = blockIdx.y & 15;
    int q0 = blockIdx.x << 7;         // 128-row q tiles
    int tid = threadIdx.x, warp = tid >> 5, lane = tid & 31;
    int gid = lane >> 2, tig = lane & 3;
    int wq = warp * 32;
    int l7 = lane & 7, l3 = lane >> 3;

    const size_t rstr = 3 * CD;
    const __half* qb = qkv + (size_t)b * CS * rstr + h * CDH;
    const __half* kb = qb + CD;
    const __half* vb = qb + 2 * CD;
    const float qscale = 1.4426950408889634f * 0.125f;   // log2e / sqrt(dh)

    // ---- stage Q through kv-stage 0 (128*72 fits exactly)
#pragma unroll
    for (int p = 0; p < 8; p++) {
        int id  = tid + p * 128;        // 0..1023
        int row = id >> 3;              // 0..127
        int c8  = (id & 7) << 3;        // 0..56
        cp16(smem_u32(&Ks[row * 72 + c8]),
             qb + (size_t)(q0 + row) * rstr + c8);
    }
    cp_commit();
    cp_wait<0>();
    __syncthreads();

    uint32_t Qbase = smem_u32(Ks);
    uint32_t qf[2][4][4];
#pragma unroll
    for (int mi = 0; mi < 2; mi++)
#pragma unroll
        for (int g4 = 0; g4 < 4; g4++) {
            uint32_t adr = Qbase +
                ((wq + mi * 16 + (l3 & 1) * 8 + l7) * 72 +
                 g4 * 16 + (l3 >> 1) * 8) * 2;
            ldsm_x4(qf[mi][g4][0], qf[mi][g4][1],
                    qf[mi][g4][2], qf[mi][g4][3], adr);
        }
    __syncthreads();

    auto load_kv = [&](int st, int kt) {
#pragma unroll
        for (int p = 0; p < 8; p++) {
            int id  = tid + p * 128;    // 0..1023
            int row = id >> 3;          // 0..127
            int c8  = (id & 7) << 3;
            cp16(smem_u32(&Ks[st * FKV + row * 72 + c8]),
                 kb + (size_t)(kt + row) * rstr + c8);
            cp16(smem_u32(&Vs[st * FKV + row * 72 + c8]),
                 vb + (size_t)(kt + row) * rstr + c8);
        }
        cp_commit();
    };

    load_kv(0, 0);
    load_kv(1, 128);

    float o[2][9][4];
#pragma unroll
    for (int mi = 0; mi < 2; mi++)
#pragma unroll
        for (int n = 0; n < 9; n++)
#pragma unroll
            for (int c = 0; c < 4; c++) o[mi][n][c] = 0.f;

    const uint32_t bones = (gid == 0) ? 0x3C003C00u : 0u;   // fp16 {1,1}
    const int nkt = CS / 128;   // 16

    for (int it = 0; it < nkt; it++) {
        int st = it & 1;
        cp_wait<1>();
        __syncthreads();

#pragma unroll
        for (int half = 0; half < 2; half++) {
            uint32_t Kbase = smem_u32(Ks + st * FKV + half * 64 * 72);
            uint32_t Vbase = smem_u32(Vs + st * FKV + half * 64 * 72);

            // S = Q @ K^T : K fragments shared across both mi
            float sc[2][8][4];
#pragma unroll
            for (int mi = 0; mi < 2; mi++)
#pragma unroll
                for (int n = 0; n < 8; n++)
#pragma unroll
                    for (int c = 0; c < 4; c++) sc[mi][n][c] = 0.f;
#pragma unroll
            for (int g4 = 0; g4 < 4; g4++) {
#pragma unroll
                for (int np = 0; np < 4; np++) {
                    uint32_t adr = Kbase +
                        ((np * 16 + (l3 & 1) * 8 + l7) * 72 +
                         g4 * 16 + (l3 >> 1) * 8) * 2;
                    uint32_t r0, r1, r2, r3;
                    ldsm_x4(r0, r1, r2, r3, adr);
                    uint32_t b0[2] = {r0, r2};
                    uint32_t b1[2] = {r1, r3};
                    mma_f16(sc[0][2 * np],     qf[0][g4], b0);
                    mma_f16(sc[0][2 * np + 1], qf[0][g4], b1);
                    mma_f16(sc[1][2 * np],     qf[1][g4], b0);
                    mma_f16(sc[1][2 * np + 1], qf[1][g4], b1);
                }
            }

            // P = exp2(S * qscale) into fp16 A-fragments
            uint32_t pf[2][4][4];
#pragma unroll
            for (int mi = 0; mi < 2; mi++)
#pragma unroll
                for (int n = 0; n < 8; n++) {
                    int t = n >> 1, hi = (n & 1) << 1;
                    pf[mi][t][hi + 0] = pack_f16(ex2f(sc[mi][n][0] * qscale),
                                                 ex2f(sc[mi][n][1] * qscale));
                    pf[mi][t][hi + 1] = pack_f16(ex2f(sc[mi][n][2] * qscale),
                                                 ex2f(sc[mi][n][3] * qscale));
                }

            // O += P @ V : V fragments shared across both mi
#pragma unroll
            for (int t = 0; t < 4; t++) {
#pragma unroll
                for (int a = 0; a < 4; a++) {
                    uint32_t adr = Vbase +
                        (16 * t + (l3 & 1) * 8 + l7) * 144 +
                        (2 * a + (l3 >> 1)) * 16;
                    uint32_t v0, v1, v2, v3;
                    ldsm_x4_t(v0, v1, v2, v3, adr);
                    uint32_t bv0[2] = {v0, v1};
                    uint32_t bv1[2] = {v2, v3};
                    mma_f16(o[0][2 * a],     pf[0][t], bv0);
                    mma_f16(o[0][2 * a + 1], pf[0][t], bv1);
                    mma_f16(o[1][2 * a],     pf[1][t], bv0);
                    mma_f16(o[1][2 * a + 1], pf[1][t], bv1);
                }
                {
                    uint32_t bv[2] = {bones, bones};
                    mma_f16(o[0][8], pf[0][t], bv);
                    mma_f16(o[1][8], pf[1][t], bv);
                }
            }
        }

        __syncthreads();
        if (it + 2 < nkt) load_kv(st, (it + 2) * 128);
        else cp_commit();
    }

    // normalize + write fp16 (row sums in tig==0 lanes of o[mi][8])
    int base = lane & 28;
#pragma unroll
    for (int mi = 0; mi < 2; mi++)
#pragma unroll
        for (int hh = 0; hh < 2; hh++) {
            float lsv = __shfl_sync(0xffffffffu, o[mi][8][hh ? 2 : 0], base);
            float inv = 1.f / lsv;
            int row = q0 + wq + mi * 16 + gid + 8 * hh;
#pragma unroll
            for (int n = 0; n < 8; n++) {
                int col = h * CDH + n * 8 + 2 * tig;
                *(uint32_t*)&out[((size_t)b * CS + row) * CD + col] =
                    pack_f16(o[mi][n][2 * hh] * inv, o[mi][n][2 * hh + 1] * inv);
            }
        }
}

// ---------------------------------------------------------------------------
// Fused residual add + LayerNorm
// ---------------------------------------------------------------------------
__global__ __launch_bounds__(256)
void add_ln(const float* __restrict__ chunk, const float* __restrict__ proj,
            const float* __restrict__ g, const float* __restrict__ beta,
            float* __restrict__ out) {
    int row = blockIdx.x;
    int tid = threadIdx.x;
    size_t base = (size_t)row * CD + tid * 4;

    float4 c = *(const float4*)&chunk[base];
    float4 p = *(const float4*)&proj[base];
    float4 x = make_float4(c.x + p.x, c.y + p.y, c.z + p.z, c.w + p.w);

    float s  = x.x + x.y + x.z + x.w;
    float s2 = x.x * x.x + x.y * x.y + x.z * x.z + x.w * x.w;
#pragma unroll
    for (int off = 16; off; off >>= 1) {
        s  += __shfl_xor_sync(0xffffffffu, s,  off);
        s2 += __shfl_xor_sync(0xffffffffu, s2, off);
    }
    __shared__ float rs[8], rs2[8];
    __shared__ float s_mu, s_rstd;
    int lane = tid & 31, warp = tid >> 5;
    if (lane == 0) { rs[warp] = s; rs2[warp] = s2; }
    __syncthreads();
    if (tid == 0) {
        float a = 0.f, b2 = 0.f;
#pragma unroll
        for (int w = 0; w < 8; w++) { a += rs[w]; b2 += rs2[w]; }
        float mean = a * (1.f / CD);
        float var  = b2 * (1.f / CD) - mean * mean;
        s_mu = mean;
        s_rstd = rsqrtf(var + LN_EPS);
    }
    __syncthreads();
    float mu = s_mu, rstd = s_rstd;

    float4 gv = *(const float4*)&g[tid * 4];
    float4 bv = *(const float4*)&beta[tid * 4];
    float4 y;
    y.x = (x.x - mu) * rstd * gv.x + bv.x;
    y.y = (x.y - mu) * rstd * gv.y + bv.y;
    y.z = (x.z - mu) * rstd * gv.z + bv.z;
    y.w = (x.w - mu) * rstd * gv.w + bv.w;
    *(float4*)&out[base] = y;
}

// ---------------------------------------------------------------------------
extern "C" void kernel_launch(void* const* d_in, const int* in_sizes, int n_in,
                              void* d_out, int out_size) {
    const float* emb     = (const float*)d_in[0];
    const float* chunk_w = (const float*)d_in[1];
    const float* chunk_b = (const float*)d_in[2];
    const float* in_w    = (const float*)d_in[3];
    const float* in_b    = (const float*)d_in[4];
    const float* out_w   = (const float*)d_in[5];
    const float* out_b   = (const float*)d_in[6];
    const float* ln_g    = (const float*)d_in[7];
    const float* ln_b    = (const float*)d_in[8];
    float* out = (float*)d_out;

    float *chunk, *proj;
    __half *emb_h, *chunk_h, *qkv_h, *attn_h, *cw_h, *iw_h, *ow_h;
    cudaGetSymbolAddress((void**)&chunk,   g_chunk);
    cudaGetSymbolAddress((void**)&proj,    g_proj);
    cudaGetSymbolAddress((void**)&emb_h,   g_emb_h);
    cudaGetSymbolAddress((void**)&chunk_h, g_chunk_h);
    cudaGetSymbolAddress((void**)&qkv_h,   g_qkv_h);
    cudaGetSymbolAddress((void**)&attn_h,  g_attn_h);
    cudaGetSymbolAddress((void**)&cw_h,    g_cw_h);
    cudaGetSymbolAddress((void**)&iw_h,    g_iw_h);
    cudaGetSymbolAddress((void**)&ow_h,    g_ow_h);

    cudaFuncSetAttribute(gemm_f16<true>,
                         cudaFuncAttributeMaxDynamicSharedMemorySize, GH_SMEM);
    cudaFuncSetAttribute(gemm_f16<false>,
                         cudaFuncAttributeMaxDynamicSharedMemorySize, GH_SMEM);
    cudaFuncSetAttribute(flash_f16,
                         cudaFuncAttributeMaxDynamicSharedMemorySize, FA_SMEM);

    // 0) fused f32 -> f16 conversions
    {
        int n0 = MROWS * CD / 8;
        int n1 = CD * 2 * CD / 8;
        int n2 = 3 * CD * CD / 8;
        int n3 = CD * CD / 8;
        int nt = n0 + n1 + n2 + n3;
        f2h4<<<(nt + 255) / 256, 256>>>(emb, emb_h, n0, chunk_w, cw_h, n1,
                                        in_w, iw_h, n2, out_w, ow_h, n3);
    }
    // 1) chunk = windows @ chunk_w^T + chunk_b  (f32 + f16 outputs)
    {
        dim3 grid(CD / 128, MROWS / 128);
        gemm_f16<true><<<grid, 128, GH_SMEM>>>(emb_h, cw_h, chunk_b,
                                               chunk, chunk_h,
                                               MROWS, CD, 2 * CD);
    }
    // 2) qkv = chunk @ in_proj_w^T + in_proj_b  (f16 output only)
    {
        dim3 grid(3 * CD / 128, MROWS / 128);
        gemm_f16<false><<<grid, 128, GH_SMEM>>>(chunk_h, iw_h, in_b,
                                                nullptr, qkv_h,
                                                MROWS, 3 * CD, CD);
    }
    // 3) flash attention (fp16 in/out, 128-row q tiles, 128 thr, 2 CTAs/SM)
    {
        dim3 grid(CS / 128, CB * CH);
        flash_f16<<<grid, 128, FA_SMEM>>>(qkv_h, attn_h);
    }
    // 4) proj = attn @ out_proj_w^T + out_proj_b  (f32 output only)
    {
        dim3 grid(CD / 128, MROWS / 128);
        gemm_f16<false><<<grid, 128, GH_SMEM>>>(attn_h, ow_h, out_b,
                                                proj, nullptr,
                                                MROWS, CD, CD);
    }
    // 5) out = LayerNorm(chunk + proj)
    add_ln<<<MROWS, 256>>>(chunk, proj, ln_g, ln_b, out);
}

// round 16
// speedup vs baseline: 1.0728x; 1.0186x over previous
#include <cuda_runtime.h>
#include <cuda_fp16.h>
#include <math.h>
#include <stdint.h>

#define CB   4
#define CS   2048
#define CD   1024
#define CH   16
#define CDH  64
#define MROWS (CB*CS)
#define LN_EPS 1e-5f

// ---------------- scratch ----------------
__device__ float  g_chunk[(size_t)MROWS*CD];          // f32 for LN
__device__ float  g_proj [(size_t)MROWS*CD];          // f32 for LN
__device__ __half g_emb_h  [(size_t)MROWS*CD];
__device__ __half g_chunk_h[(size_t)MROWS*CD];
__device__ __half g_qkv_h  [(size_t)MROWS*3*CD];
__device__ __half g_attn_h [(size_t)MROWS*CD];
__device__ __half g_cw_h[(size_t)CD*2*CD];
__device__ __half g_iw_h[(size_t)3*CD*CD];
__device__ __half g_ow_h[(size_t)CD*CD];

// ---------------- helpers ----------------
__device__ __forceinline__ float ex2f(float x) {
    float y; asm("ex2.approx.f32 %0, %1;" : "=f"(y) : "f"(x)); return y;
}
__device__ __forceinline__ uint32_t pack_f16(float lo, float hi) {
    uint32_t r; asm("cvt.rn.f16x2.f32 %0, %1, %2;" : "=r"(r) : "f"(hi), "f"(lo));
    return r;
}
__device__ __forceinline__ void mma_f16(float c[4], const uint32_t a[4],
                                        const uint32_t b[2]) {
    asm volatile(
        "mma.sync.aligned.m16n8k16.row.col.f32.f16.f16.f32 "
        "{%0,%1,%2,%3}, {%4,%5,%6,%7}, {%8,%9}, {%0,%1,%2,%3};\n"
        : "+f"(c[0]), "+f"(c[1]), "+f"(c[2]), "+f"(c[3])
        : "r"(a[0]), "r"(a[1]), "r"(a[2]), "r"(a[3]), "r"(b[0]), "r"(b[1]));
}
__device__ __forceinline__ void ldsm_x4(uint32_t& r0, uint32_t& r1,
                                        uint32_t& r2, uint32_t& r3,
                                        uint32_t addr) {
    asm volatile("ldmatrix.sync.aligned.m8n8.x4.shared.b16 {%0,%1,%2,%3}, [%4];\n"
                 : "=r"(r0), "=r"(r1), "=r"(r2), "=r"(r3) : "r"(addr));
}
__device__ __forceinline__ void ldsm_x4_t(uint32_t& r0, uint32_t& r1,
                                          uint32_t& r2, uint32_t& r3,
                                          uint32_t addr) {
    asm volatile("ldmatrix.sync.aligned.m8n8.x4.trans.shared.b16 {%0,%1,%2,%3}, [%4];\n"
                 : "=r"(r0), "=r"(r1), "=r"(r2), "=r"(r3) : "r"(addr));
}
__device__ __forceinline__ uint32_t smem_u32(const void* p) {
    return (uint32_t)__cvta_generic_to_shared(p);
}
__device__ __forceinline__ void cp16(uint32_t dst, const void* src) {
    asm volatile("cp.async.cg.shared.global [%0], [%1], 16;\n"
                 :: "r"(dst), "l"(src));
}
__device__ __forceinline__ void cp16z(uint32_t dst, const void* src, int srcsz) {
    asm volatile("cp.async.cg.shared.global [%0], [%1], 16, %2;\n"
                 :: "r"(dst), "l"(src), "r"(srcsz));
}
__device__ __forceinline__ void cp_commit() {
    asm volatile("cp.async.commit_group;\n");
}
template<int N> __device__ __forceinline__ void cp_wait() {
    asm volatile("cp.async.wait_group %0;\n" :: "n"(N));
}

// ---------------------------------------------------------------------------
// fused f32 -> f16 convert for all 4 tensors (8 elems/thread)
// ---------------------------------------------------------------------------
__global__ __launch_bounds__(256)
void f2h4(const float* __restrict__ s0, __half* __restrict__ d0, int n0,
          const float* __restrict__ s1, __half* __restrict__ d1, int n1,
          const float* __restrict__ s2, __half* __restrict__ d2, int n2,
          const float* __restrict__ s3, __half* __restrict__ d3, int n3) {
    int i = blockIdx.x * 256 + threadIdx.x;
    const float* s; __half* d; int j = i;
    if (j < n0)                { s = s0; d = d0; }
    else if ((j -= n0) < n1)   { s = s1; d = d1; }
    else if ((j -= n1) < n2)   { s = s2; d = d2; }
    else if ((j -= n2) < n3)   { s = s3; d = d3; }
    else return;
    float4 a = ((const float4*)s)[2 * j];
    float4 b = ((const float4*)s)[2 * j + 1];
    uint4 o;
    o.x = pack_f16(a.x, a.y); o.y = pack_f16(a.z, a.w);
    o.z = pack_f16(b.x, b.y); o.w = pack_f16(b.z, b.w);
    ((uint4*)d)[j] = o;
}

// ---------------------------------------------------------------------------
// FP16 NT GEMM: 128x128x64 tile, 128 threads, 64x64 warp tile, 3-stage ring.
// fp16 output optionally scales columns < lo_cols by lo_scale (qscale fold).
// ---------------------------------------------------------------------------
#define GSTGH (128 * 72)                 // halves per stage per matrix
#define GH_SMEM (3 * 2 * GSTGH * 2)      // 110592 B

template<bool WINDOW>
__global__ __launch_bounds__(128, 2)
void gemm_f16(const __half* __restrict__ A, const __half* __restrict__ B,
              const float* __restrict__ bias,
              float* __restrict__ Cf, __half* __restrict__ Ch,
              int M, int N, int K, int lo_cols, float lo_scale) {
    extern __shared__ __half smh[];
    __half* As = smh;                 // [3][128][72]
    __half* Bs = smh + 3 * GSTGH;     // [3][128][72]

    int tid = threadIdx.x;
    int bm = blockIdx.y * 128, bn = blockIdx.x * 128;
    int warp = tid >> 5, lane = tid & 31, gid = lane >> 2, tig = lane & 3;
    int l7 = lane & 7, l3 = lane >> 3;
    int wm = (warp >> 1) * 64, wn = (warp & 1) * 64;

    float acc[4][8][4];
#pragma unroll
    for (int i = 0; i < 4; i++)
#pragma unroll
        for (int j = 0; j < 8; j++)
#pragma unroll
            for (int c = 0; c < 4; c++) acc[i][j][c] = 0.f;

    auto load_stage = [&](int st, int k0) {
#pragma unroll
        for (int p = 0; p < 8; p++) {
            int id  = tid + p * 128;        // 0..1023
            int row = id >> 3;              // 0..127
            int kq  = (id & 7) << 3;        // 0..56 halves
            uint32_t da = smem_u32(&As[st * GSTGH + row * 72 + kq]);
            if (WINDOW) {
                int m = bm + row;
                int bidx = m >> 11, s = m & (CS - 1);
                int f = k0 + kq, kk = f >> 10, j = f & (CD - 1);
                const __half* src = A + (((size_t)bidx * CS + s + kk) << 10) + j;
                cp16z(da, src, (s + kk < CS) ? 16 : 0);
            } else {
                cp16(da, A + (size_t)(bm + row) * K + k0 + kq);
            }
            cp16(smem_u32(&Bs[st * GSTGH + row * 72 + kq]),
                 B + (size_t)(bn + row) * K + k0 + kq);
        }
        cp_commit();
    };

    int nk = K >> 6;   // BK=64
    load_stage(0, 0);
    load_stage(1, 64);

    int st = 0, pfst = 2;
    for (int kc = 0; kc < nk; kc++) {
        cp_wait<1>();
        __syncthreads();

        int pf = kc + 2;
        if (pf < nk) load_stage(pfst, pf << 6);
        else cp_commit();

        uint32_t Abase = smem_u32(As + st * GSTGH);
        uint32_t Bbase = smem_u32(Bs + st * GSTGH);
#pragma unroll
        for (int g = 0; g < 64; g += 16) {
            uint32_t a[4][4], bf[8][2];
#pragma unroll
            for (int ti = 0; ti < 4; ti++) {
                uint32_t adr = Abase +
                    ((wm + ti * 16 + (l3 & 1) * 8 + l7) * 72 +
                     g + (l3 >> 1) * 8) * 2;
                ldsm_x4(a[ti][0], a[ti][1], a[ti][2], a[ti][3], adr);
            }
#pragma unroll
            for (int tp = 0; tp < 4; tp++) {
                uint32_t adr = Bbase +
                    ((wn + tp * 16 + (l3 & 1) * 8 + l7) * 72 +
                     g + (l3 >> 1) * 8) * 2;
                uint32_t r0, r1, r2, r3;
                ldsm_x4(r0, r1, r2, r3, adr);
                bf[2 * tp][0] = r0; bf[2 * tp][1] = r2;
                bf[2 * tp + 1][0] = r1; bf[2 * tp + 1][1] = r3;
            }
#pragma unroll
            for (int ti = 0; ti < 4; ti++)
#pragma unroll
                for (int tj = 0; tj < 8; tj++)
                    mma_f16(acc[ti][tj], a[ti], bf[tj]);
        }

        st   = (st   == 2) ? 0 : st + 1;
        pfst = (pfst == 2) ? 0 : pfst + 1;
    }

#pragma unroll
    for (int ti = 0; ti < 4; ti++) {
#pragma unroll
        for (int hh = 0; hh < 2; hh++) {
            int row = bm + wm + ti * 16 + gid + 8 * hh;
#pragma unroll
            for (int tj = 0; tj < 8; tj++) {
                int col = bn + wn + tj * 8 + 2 * tig;
                float ox = acc[ti][tj][2 * hh + 0] + bias[col + 0];
                float oy = acc[ti][tj][2 * hh + 1] + bias[col + 1];
                if (Cf) *(float2*)&Cf[(size_t)row * N + col] = make_float2(ox, oy);
                if (Ch) {
                    float sc = (col < lo_cols) ? lo_scale : 1.f;
                    *(uint32_t*)&Ch[(size_t)row * N + col] =
                        pack_f16(ox * sc, oy * sc);
                }
            }
        }
    }
}

// ---------------------------------------------------------------------------
// FP16 flash attention, mi=2, per-np fused S->exp->PV (np == PV t index).
// 4 warps x 32 q-rows, 128 thr, 3 CTAs/SM (reg cap 170; peak ~150).
// Q pre-scaled by log2e/sqrt(dh) in the qkv GEMM epilogue.
// kv tiles of 128 (two 64-row halves), 2-stage ring.
// ---------------------------------------------------------------------------
#define FKV (128 * 72)                      // halves per stage per matrix
#define FA_SMEM (2 * 2 * FKV * 2)           // 73728 B

__global__ __launch_bounds__(128, 3)
void flash_f16(const __half* __restrict__ qkv, __half* __restrict__ out) {
    extern __shared__ __half smh[];
    __half* Ks = smh;                 // [2][128][72]
    __half* Vs = smh + 2 * FKV;       // [2][128][72]

    int b = blockIdx.y >> 4, h = blockIdx.y & 15;
    int q0 = blockIdx.x << 7;         // 128-row q tiles
    int tid = threadIdx.x, warp = tid >> 5, lane = tid & 31;
    int gid = lane >> 2, tig = lane & 3;
    int wq = warp * 32;
    int l7 = lane & 7, l3 = lane >> 3;

    const size_t rstr = 3 * CD;
    const __half* qb = qkv + (size_t)b * CS * rstr + h * CDH;
    const __half* kb = qb + CD;
    const __half* vb = qb + 2 * CD;

    // ---- stage Q through kv-stage 0 (128*72 fits exactly)
#pragma unroll
    for (int p = 0; p < 8; p++) {
        int id  = tid + p * 128;        // 0..1023
        int row = id >> 3;              // 0..127
        int c8  = (id & 7) << 3;        // 0..56
        cp16(smem_u32(&Ks[row * 72 + c8]),
             qb + (size_t)(q0 + row) * rstr + c8);
    }
    cp_commit();
    cp_wait<0>();
    __syncthreads();

    uint32_t Qbase = smem_u32(Ks);
    uint32_t qf[2][4][4];
#pragma unroll
    for (int mi = 0; mi < 2; mi++)
#pragma unroll
        for (int g4 = 0; g4 < 4; g4++) {
            uint32_t adr = Qbase +
                ((wq + mi * 16 + (l3 & 1) * 8 + l7) * 72 +
                 g4 * 16 + (l3 >> 1) * 8) * 2;
            ldsm_x4(qf[mi][g4][0], qf[mi][g4][1],
                    qf[mi][g4][2], qf[mi][g4][3], adr);
        }
    __syncthreads();

    auto load_kv = [&](int st, int kt) {
#pragma unroll
        for (int p = 0; p < 8; p++) {
            int id  = tid + p * 128;    // 0..1023
            int row = id >> 3;          // 0..127
            int c8  = (id & 7) << 3;
            cp16(smem_u32(&Ks[st * FKV + row * 72 + c8]),
                 kb + (size_t)(kt + row) * rstr + c8);
            cp16(smem_u32(&Vs[st * FKV + row * 72 + c8]),
                 vb + (size_t)(kt + row) * rstr + c8);
        }
        cp_commit();
    };

    load_kv(0, 0);
    load_kv(1, 128);

    float o[2][9][4];
#pragma unroll
    for (int mi = 0; mi < 2; mi++)
#pragma unroll
        for (int n = 0; n < 9; n++)
#pragma unroll
            for (int c = 0; c < 4; c++) o[mi][n][c] = 0.f;

    const uint32_t bones = (gid == 0) ? 0x3C003C00u : 0u;   // fp16 {1,1}
    const int nkt = CS / 128;   // 16

    for (int it = 0; it < nkt; it++) {
        int st = it & 1;
        cp_wait<1>();
        __syncthreads();

#pragma unroll
        for (int half = 0; half < 2; half++) {
            uint32_t Kbase = smem_u32(Ks + st * FKV + half * 64 * 72);
            uint32_t Vbase = smem_u32(Vs + st * FKV + half * 64 * 72);

            // per-np (== PV t): S chunk -> exp -> PV chunk; pf dies each np
#pragma unroll
            for (int np = 0; np < 4; np++) {
                float sc[2][2][4];
#pragma unroll
                for (int mi = 0; mi < 2; mi++)
#pragma unroll
                    for (int nn = 0; nn < 2; nn++)
#pragma unroll
                        for (int c = 0; c < 4; c++) sc[mi][nn][c] = 0.f;
#pragma unroll
                for (int g4 = 0; g4 < 4; g4++) {
                    uint32_t adr = Kbase +
                        ((np * 16 + (l3 & 1) * 8 + l7) * 72 +
                         g4 * 16 + (l3 >> 1) * 8) * 2;
                    uint32_t r0, r1, r2, r3;
                    ldsm_x4(r0, r1, r2, r3, adr);
                    uint32_t b0[2] = {r0, r2};
                    uint32_t b1[2] = {r1, r3};
                    mma_f16(sc[0][0], qf[0][g4], b0);
                    mma_f16(sc[0][1], qf[0][g4], b1);
                    mma_f16(sc[1][0], qf[1][g4], b0);
                    mma_f16(sc[1][1], qf[1][g4], b1);
                }

                uint32_t pf[2][4];
#pragma unroll
                for (int mi = 0; mi < 2; mi++) {
                    pf[mi][0] = pack_f16(ex2f(sc[mi][0][0]), ex2f(sc[mi][0][1]));
                    pf[mi][1] = pack_f16(ex2f(sc[mi][0][2]), ex2f(sc[mi][0][3]));
                    pf[mi][2] = pack_f16(ex2f(sc[mi][1][0]), ex2f(sc[mi][1][1]));
                    pf[mi][3] = pack_f16(ex2f(sc[mi][1][2]), ex2f(sc[mi][1][3]));
                }

                // PV chunk t = np
#pragma unroll
                for (int a = 0; a < 4; a++) {
                    uint32_t adr = Vbase +
                        (16 * np + (l3 & 1) * 8 + l7) * 144 +
                        (2 * a + (l3 >> 1)) * 16;
                    uint32_t v0, v1, v2, v3;
                    ldsm_x4_t(v0, v1, v2, v3, adr);
                    uint32_t bv0[2] = {v0, v1};
                    uint32_t bv1[2] = {v2, v3};
                    mma_f16(o[0][2 * a],     pf[0], bv0);
                    mma_f16(o[0][2 * a + 1], pf[0], bv1);
                    mma_f16(o[1][2 * a],     pf[1], bv0);
                    mma_f16(o[1][2 * a + 1], pf[1], bv1);
                }
                {
                    uint32_t bv[2] = {bones, bones};
                    mma_f16(o[0][8], pf[0], bv);
                    mma_f16(o[1][8], pf[1], bv);
                }
            }
        }

        __syncthreads();
        if (it + 2 < nkt) load_kv(st, (it + 2) * 128);
        else cp_commit();
    }

    // normalize + write fp16 (row sums in tig==0 lanes of o[mi][8])
    int base = lane & 28;
#pragma unroll
    for (int mi = 0; mi < 2; mi++)
#pragma unroll
        for (int hh = 0; hh < 2; hh++) {
            float lsv = __shfl_sync(0xffffffffu, o[mi][8][hh ? 2 : 0], base);
            float inv = 1.f / lsv;
            int row = q0 + wq + mi * 16 + gid + 8 * hh;
#pragma unroll
            for (int n = 0; n < 8; n++) {
                int col = h * CDH + n * 8 + 2 * tig;
                *(uint32_t*)&out[((size_t)b * CS + row) * CD + col] =
                    pack_f16(o[mi][n][2 * hh] * inv, o[mi][n][2 * hh + 1] * inv);
            }
        }
}

// ---------------------------------------------------------------------------
// Fused residual add + LayerNorm
// ---------------------------------------------------------------------------
__global__ __launch_bounds__(256)
void add_ln(const float* __restrict__ chunk, const float* __restrict__ proj,
            const float* __restrict__ g, const float* __restrict__ beta,
            float* __restrict__ out) {
    int row = blockIdx.x;
    int tid = threadIdx.x;
    size_t base = (size_t)row * CD + tid * 4;

    float4 c = *(const float4*)&chunk[base];
    float4 p = *(const float4*)&proj[base];
    float4 x = make_float4(c.x + p.x, c.y + p.y, c.z + p.z, c.w + p.w);

    float s  = x.x + x.y + x.z + x.w;
    float s2 = x.x * x.x + x.y * x.y + x.z * x.z + x.w * x.w;
#pragma unroll
    for (int off = 16; off; off >>= 1) {
        s  += __shfl_xor_sync(0xffffffffu, s,  off);
        s2 += __shfl_xor_sync(0xffffffffu, s2, off);
    }
    __shared__ float rs[8], rs2[8];
    __shared__ float s_mu, s_rstd;
    int lane = tid & 31, warp = tid >> 5;
    if (lane == 0) { rs[warp] = s; rs2[warp] = s2; }
    __syncthreads();
    if (tid == 0) {
        float a = 0.f, b2 = 0.f;
#pragma unroll
        for (int w = 0; w < 8; w++) { a += rs[w]; b2 += rs2[w]; }
        float mean = a * (1.f / CD);
        float var  = b2 * (1.f / CD) - mean * mean;
        s_mu = mean;
        s_rstd = rsqrtf(var + LN_EPS);
    }
    __syncthreads();
    float mu = s_mu, rstd = s_rstd;

    float4 gv = *(const float4*)&g[tid * 4];
    float4 bv = *(const float4*)&beta[tid * 4];
    float4 y;
    y.x = (x.x - mu) * rstd * gv.x + bv.x;
    y.y = (x.y - mu) * rstd * gv.y + bv.y;
    y.z = (x.z - mu) * rstd * gv.z + bv.z;
    y.w = (x.w - mu) * rstd * gv.w + bv.w;
    *(float4*)&out[base] = y;
}

// ---------------------------------------------------------------------------
extern "C" void kernel_launch(void* const* d_in, const int* in_sizes, int n_in,
                              void* d_out, int out_size) {
    const float* emb     = (const float*)d_in[0];
    const float* chunk_w = (const float*)d_in[1];
    const float* chunk_b = (const float*)d_in[2];
    const float* in_w    = (const float*)d_in[3];
    const float* in_b    = (const float*)d_in[4];
    const float* out_w   = (const float*)d_in[5];
    const float* out_b   = (const float*)d_in[6];
    const float* ln_g    = (const float*)d_in[7];
    const float* ln_b    = (const float*)d_in[8];
    float* out = (float*)d_out;

    float *chunk, *proj;
    __half *emb_h, *chunk_h, *qkv_h, *attn_h, *cw_h, *iw_h, *ow_h;
    cudaGetSymbolAddress((void**)&chunk,   g_chunk);
    cudaGetSymbolAddress((void**)&proj,    g_proj);
    cudaGetSymbolAddress((void**)&emb_h,   g_emb_h);
    cudaGetSymbolAddress((void**)&chunk_h, g_chunk_h);
    cudaGetSymbolAddress((void**)&qkv_h,   g_qkv_h);
    cudaGetSymbolAddress((void**)&attn_h,  g_attn_h);
    cudaGetSymbolAddress((void**)&cw_h,    g_cw_h);
    cudaGetSymbolAddress((void**)&iw_h,    g_iw_h);
    cudaGetSymbolAddress((void**)&ow_h,    g_ow_h);

    cudaFuncSetAttribute(gemm_f16<true>,
                         cudaFuncAttributeMaxDynamicSharedMemorySize, GH_SMEM);
    cudaFuncSetAttribute(gemm_f16<false>,
                         cudaFuncAttributeMaxDynamicSharedMemorySize, GH_SMEM);
    cudaFuncSetAttribute(flash_f16,
                         cudaFuncAttributeMaxDynamicSharedMemorySize, FA_SMEM);

    const float qscale = 1.4426950408889634f * 0.125f;   // log2e / sqrt(dh)

    // 0) fused f32 -> f16 conversions
    {
        int n0 = MROWS * CD / 8;
        int n1 = CD * 2 * CD / 8;
        int n2 = 3 * CD * CD / 8;
        int n3 = CD * CD / 8;
        int nt = n0 + n1 + n2 + n3;
        f2h4<<<(nt + 255) / 256, 256>>>(emb, emb_h, n0, chunk_w, cw_h, n1,
                                        in_w, iw_h, n2, out_w, ow_h, n3);
    }
    // 1) chunk = windows @ chunk_w^T + chunk_b  (f32 + f16 outputs)
    {
        dim3 grid(CD / 128, MROWS / 128);
        gemm_f16<true><<<grid, 128, GH_SMEM>>>(emb_h, cw_h, chunk_b,
                                               chunk, chunk_h,
                                               MROWS, CD, 2 * CD, 0, 1.f);
    }
    // 2) qkv = chunk @ in_proj_w^T + in_proj_b  (f16 out; q-cols pre-scaled)
    {
        dim3 grid(3 * CD / 128, MROWS / 128);
        gemm_f16<false><<<grid, 128, GH_SMEM>>>(chunk_h, iw_h, in_b,
                                                nullptr, qkv_h,
                                                MROWS, 3 * CD, CD, CD, qscale);
    }
    // 3) flash attention (fp16 in/out, 128-row q tiles, 128 thr, 3 CTAs/SM)
    {
        dim3 grid(CS / 128, CB * CH);
        flash_f16<<<grid, 128, FA_SMEM>>>(qkv_h, attn_h);
    }
    // 4) proj = attn @ out_proj_w^T + out_proj_b  (f32 output only)
    {
        dim3 grid(CD / 128, MROWS / 128);
        gemm_f16<false><<<grid, 128, GH_SMEM>>>(attn_h, ow_h, out_b,
                                                proj, nullptr,
                                                MROWS, CD, CD, 0, 1.f);
    }
    // 5) out = LayerNorm(chunk + proj)
    add_ln<<<MROWS, 256>>>(chunk, proj, ln_g, ln_b, out);
}

// round 17
// speedup vs baseline: 1.0946x; 1.0203x over previous
#include <cuda_runtime.h>
#include <cuda_fp16.h>
#include <math.h>
#include <stdint.h>

#define CB   4
#define CS   2048
#define CD   1024
#define CH   16
#define CDH  64
#define MROWS (CB*CS)
#define LN_EPS 1e-5f

// ---------------- scratch ----------------
__device__ float  g_chunk[(size_t)MROWS*CD];          // f32 for LN
__device__ float  g_proj [(size_t)MROWS*CD];          // f32 for LN
__device__ __half g_emb_h  [(size_t)MROWS*CD];
__device__ __half g_chunk_h[(size_t)MROWS*CD];
__device__ __half g_qkv_h  [(size_t)MROWS*3*CD];
__device__ __half g_attn_h [(size_t)MROWS*CD];
__device__ __half g_cw_h[(size_t)CD*2*CD];
__device__ __half g_iw_h[(size_t)3*CD*CD];
__device__ __half g_ow_h[(size_t)CD*CD];

// ---------------- helpers ----------------
__device__ __forceinline__ uint32_t pack_f16(float lo, float hi) {
    uint32_t r; asm("cvt.rn.f16x2.f32 %0, %1, %2;" : "=r"(r) : "f"(hi), "f"(lo));
    return r;
}
__device__ __forceinline__ uint32_t ex2_h2(uint32_t x) {
    uint32_t y; asm("ex2.approx.f16x2 %0, %1;" : "=r"(y) : "r"(x));
    return y;
}
__device__ __forceinline__ void mma_f16(float c[4], const uint32_t a[4],
                                        const uint32_t b[2]) {
    asm volatile(
        "mma.sync.aligned.m16n8k16.row.col.f32.f16.f16.f32 "
        "{%0,%1,%2,%3}, {%4,%5,%6,%7}, {%8,%9}, {%0,%1,%2,%3};\n"
        : "+f"(c[0]), "+f"(c[1]), "+f"(c[2]), "+f"(c[3])
        : "r"(a[0]), "r"(a[1]), "r"(a[2]), "r"(a[3]), "r"(b[0]), "r"(b[1]));
}
__device__ __forceinline__ void ldsm_x4(uint32_t& r0, uint32_t& r1,
                                        uint32_t& r2, uint32_t& r3,
                                        uint32_t addr) {
    asm volatile("ldmatrix.sync.aligned.m8n8.x4.shared.b16 {%0,%1,%2,%3}, [%4];\n"
                 : "=r"(r0), "=r"(r1), "=r"(r2), "=r"(r3) : "r"(addr));
}
__device__ __forceinline__ void ldsm_x4_t(uint32_t& r0, uint32_t& r1,
                                          uint32_t& r2, uint32_t& r3,
                                          uint32_t addr) {
    asm volatile("ldmatrix.sync.aligned.m8n8.x4.trans.shared.b16 {%0,%1,%2,%3}, [%4];\n"
                 : "=r"(r0), "=r"(r1), "=r"(r2), "=r"(r3) : "r"(addr));
}
__device__ __forceinline__ uint32_t smem_u32(const void* p) {
    return (uint32_t)__cvta_generic_to_shared(p);
}
__device__ __forceinline__ void cp16(uint32_t dst, const void* src) {
    asm volatile("cp.async.cg.shared.global [%0], [%1], 16;\n"
                 :: "r"(dst), "l"(src));
}
__device__ __forceinline__ void cp16z(uint32_t dst, const void* src, int srcsz) {
    asm volatile("cp.async.cg.shared.global [%0], [%1], 16, %2;\n"
                 :: "r"(dst), "l"(src), "r"(srcsz));
}
__device__ __forceinline__ void cp_commit() {
    asm volatile("cp.async.commit_group;\n");
}
template<int N> __device__ __forceinline__ void cp_wait() {
    asm volatile("cp.async.wait_group %0;\n" :: "n"(N));
}

// ---------------------------------------------------------------------------
// fused f32 -> f16 convert for all 4 tensors (8 elems/thread)
// ---------------------------------------------------------------------------
__global__ __launch_bounds__(256)
void f2h4(const float* __restrict__ s0, __half* __restrict__ d0, int n0,
          const float* __restrict__ s1, __half* __restrict__ d1, int n1,
          const float* __restrict__ s2, __half* __restrict__ d2, int n2,
          const float* __restrict__ s3, __half* __restrict__ d3, int n3) {
    int i = blockIdx.x * 256 + threadIdx.x;
    const float* s; __half* d; int j = i;
    if (j < n0)                { s = s0; d = d0; }
    else if ((j -= n0) < n1)   { s = s1; d = d1; }
    else if ((j -= n1) < n2)   { s = s2; d = d2; }
    else if ((j -= n2) < n3)   { s = s3; d = d3; }
    else return;
    float4 a = ((const float4*)s)[2 * j];
    float4 b = ((const float4*)s)[2 * j + 1];
    uint4 o;
    o.x = pack_f16(a.x, a.y); o.y = pack_f16(a.z, a.w);
    o.z = pack_f16(b.x, b.y); o.w = pack_f16(b.z, b.w);
    ((uint4*)d)[j] = o;
}

// ---------------------------------------------------------------------------
// FP16 NT GEMM: 128x128x64 tile, 128 threads, 64x64 warp tile, 3-stage ring.
// fp16 output optionally scales columns < lo_cols by lo_scale (qscale fold).
// ---------------------------------------------------------------------------
#define GSTGH (128 * 72)                 // halves per stage per matrix
#define GH_SMEM (3 * 2 * GSTGH * 2)      // 110592 B

template<bool WINDOW>
__global__ __launch_bounds__(128, 2)
void gemm_f16(const __half* __restrict__ A, const __half* __restrict__ B,
              const float* __restrict__ bias,
              float* __restrict__ Cf, __half* __restrict__ Ch,
              int M, int N, int K, int lo_cols, float lo_scale) {
    extern __shared__ __half smh[];
    __half* As = smh;                 // [3][128][72]
    __half* Bs = smh + 3 * GSTGH;     // [3][128][72]

    int tid = threadIdx.x;
    int bm = blockIdx.y * 128, bn = blockIdx.x * 128;
    int warp = tid >> 5, lane = tid & 31, gid = lane >> 2, tig = lane & 3;
    int l7 = lane & 7, l3 = lane >> 3;
    int wm = (warp >> 1) * 64, wn = (warp & 1) * 64;

    float acc[4][8][4];
#pragma unroll
    for (int i = 0; i < 4; i++)
#pragma unroll
        for (int j = 0; j < 8; j++)
#pragma unroll
            for (int c = 0; c < 4; c++) acc[i][j][c] = 0.f;

    auto load_stage = [&](int st, int k0) {
#pragma unroll
        for (int p = 0; p < 8; p++) {
            int id  = tid + p * 128;        // 0..1023
            int row = id >> 3;              // 0..127
            int kq  = (id & 7) << 3;        // 0..56 halves
            uint32_t da = smem_u32(&As[st * GSTGH + row * 72 + kq]);
            if (WINDOW) {
                int m = bm + row;
                int bidx = m >> 11, s = m & (CS - 1);
                int f = k0 + kq, kk = f >> 10, j = f & (CD - 1);
                const __half* src = A + (((size_t)bidx * CS + s + kk) << 10) + j;
                cp16z(da, src, (s + kk < CS) ? 16 : 0);
            } else {
                cp16(da, A + (size_t)(bm + row) * K + k0 + kq);
            }
            cp16(smem_u32(&Bs[st * GSTGH + row * 72 + kq]),
                 B + (size_t)(bn + row) * K + k0 + kq);
        }
        cp_commit();
    };

    int nk = K >> 6;   // BK=64
    load_stage(0, 0);
    load_stage(1, 64);

    int st = 0, pfst = 2;
    for (int kc = 0; kc < nk; kc++) {
        cp_wait<1>();
        __syncthreads();

        int pf = kc + 2;
        if (pf < nk) load_stage(pfst, pf << 6);
        else cp_commit();

        uint32_t Abase = smem_u32(As + st * GSTGH);
        uint32_t Bbase = smem_u32(Bs + st * GSTGH);
#pragma unroll
        for (int g = 0; g < 64; g += 16) {
            uint32_t a[4][4], bf[8][2];
#pragma unroll
            for (int ti = 0; ti < 4; ti++) {
                uint32_t adr = Abase +
                    ((wm + ti * 16 + (l3 & 1) * 8 + l7) * 72 +
                     g + (l3 >> 1) * 8) * 2;
                ldsm_x4(a[ti][0], a[ti][1], a[ti][2], a[ti][3], adr);
            }
#pragma unroll
            for (int tp = 0; tp < 4; tp++) {
                uint32_t adr = Bbase +
                    ((wn + tp * 16 + (l3 & 1) * 8 + l7) * 72 +
                     g + (l3 >> 1) * 8) * 2;
                uint32_t r0, r1, r2, r3;
                ldsm_x4(r0, r1, r2, r3, adr);
                bf[2 * tp][0] = r0; bf[2 * tp][1] = r2;
                bf[2 * tp + 1][0] = r1; bf[2 * tp + 1][1] = r3;
            }
#pragma unroll
            for (int ti = 0; ti < 4; ti++)
#pragma unroll
                for (int tj = 0; tj < 8; tj++)
                    mma_f16(acc[ti][tj], a[ti], bf[tj]);
        }

        st   = (st   == 2) ? 0 : st + 1;
        pfst = (pfst == 2) ? 0 : pfst + 1;
    }

#pragma unroll
    for (int ti = 0; ti < 4; ti++) {
#pragma unroll
        for (int hh = 0; hh < 2; hh++) {
            int row = bm + wm + ti * 16 + gid + 8 * hh;
#pragma unroll
            for (int tj = 0; tj < 8; tj++) {
                int col = bn + wn + tj * 8 + 2 * tig;
                float ox = acc[ti][tj][2 * hh + 0] + bias[col + 0];
                float oy = acc[ti][tj][2 * hh + 1] + bias[col + 1];
                if (Cf) *(float2*)&Cf[(size_t)row * N + col] = make_float2(ox, oy);
                if (Ch) {
                    float sc = (col < lo_cols) ? lo_scale : 1.f;
                    *(uint32_t*)&Ch[(size_t)row * N + col] =
                        pack_f16(ox * sc, oy * sc);
                }
            }
        }
    }
}

// ---------------------------------------------------------------------------
// FP16 flash attention, mi=2, per-np fused S->exp->PV (np == PV t index).
// 4 warps x 32 q-rows, 128 thr, 3 CTAs/SM.
// exp via ex2.approx.f16x2 (half the MUFU ops of f32 ex2).
// Q pre-scaled by log2e/sqrt(dh) in the qkv GEMM epilogue.
// kv tiles of 128 (two 64-row halves), 2-stage ring.
// ---------------------------------------------------------------------------
#define FKV (128 * 72)                      // halves per stage per matrix
#define FA_SMEM (2 * 2 * FKV * 2)           // 73728 B

__global__ __launch_bounds__(128, 3)
void flash_f16(const __half* __restrict__ qkv, __half* __restrict__ out) {
    extern __shared__ __half smh[];
    __half* Ks = smh;                 // [2][128][72]
    __half* Vs = smh + 2 * FKV;       // [2][128][72]

    int b = blockIdx.y >> 4, h = blockIdx.y & 15;
    int q0 = blockIdx.x << 7;         // 128-row q tiles
    int tid = threadIdx.x, warp = tid >> 5, lane = tid & 31;
    int gid = lane >> 2, tig = lane & 3;
    int wq = warp * 32;
    int l7 = lane & 7, l3 = lane >> 3;

    const size_t rstr = 3 * CD;
    const __half* qb = qkv + (size_t)b * CS * rstr + h * CDH;
    const __half* kb = qb + CD;
    const __half* vb = qb + 2 * CD;

    // ---- stage Q through kv-stage 0 (128*72 fits exactly)
#pragma unroll
    for (int p = 0; p < 8; p++) {
        int id  = tid + p * 128;        // 0..1023
        int row = id >> 3;              // 0..127
        int c8  = (id & 7) << 3;        // 0..56
        cp16(smem_u32(&Ks[row * 72 + c8]),
             qb + (size_t)(q0 + row) * rstr + c8);
    }
    cp_commit();
    cp_wait<0>();
    __syncthreads();

    uint32_t Qbase = smem_u32(Ks);
    uint32_t qf[2][4][4];
#pragma unroll
    for (int mi = 0; mi < 2; mi++)
#pragma unroll
        for (int g4 = 0; g4 < 4; g4++) {
            uint32_t adr = Qbase +
                ((wq + mi * 16 + (l3 & 1) * 8 + l7) * 72 +
                 g4 * 16 + (l3 >> 1) * 8) * 2;
            ldsm_x4(qf[mi][g4][0], qf[mi][g4][1],
                    qf[mi][g4][2], qf[mi][g4][3], adr);
        }
    __syncthreads();

    auto load_kv = [&](int st, int kt) {
#pragma unroll
        for (int p = 0; p < 8; p++) {
            int id  = tid + p * 128;    // 0..1023
            int row = id >> 3;          // 0..127
            int c8  = (id & 7) << 3;
            cp16(smem_u32(&Ks[st * FKV + row * 72 + c8]),
                 kb + (size_t)(kt + row) * rstr + c8);
            cp16(smem_u32(&Vs[st * FKV + row * 72 + c8]),
                 vb + (size_t)(kt + row) * rstr + c8);
        }
        cp_commit();
    };

    load_kv(0, 0);
    load_kv(1, 128);

    float o[2][9][4];
#pragma unroll
    for (int mi = 0; mi < 2; mi++)
#pragma unroll
        for (int n = 0; n < 9; n++)
#pragma unroll
            for (int c = 0; c < 4; c++) o[mi][n][c] = 0.f;

    const uint32_t bones = (gid == 0) ? 0x3C003C00u : 0u;   // fp16 {1,1}
    const int nkt = CS / 128;   // 16

    for (int it = 0; it < nkt; it++) {
        int st = it & 1;
        cp_wait<1>();
        __syncthreads();

#pragma unroll
        for (int half = 0; half < 2; half++) {
            uint32_t Kbase = smem_u32(Ks + st * FKV + half * 64 * 72);
            uint32_t Vbase = smem_u32(Vs + st * FKV + half * 64 * 72);

            // per-np (== PV t): S chunk -> exp(f16x2) -> PV chunk
#pragma unroll
            for (int np = 0; np < 4; np++) {
                float sc[2][2][4];
#pragma unroll
                for (int mi = 0; mi < 2; mi++)
#pragma unroll
                    for (int nn = 0; nn < 2; nn++)
#pragma unroll
                        for (int c = 0; c < 4; c++) sc[mi][nn][c] = 0.f;
#pragma unroll
                for (int g4 = 0; g4 < 4; g4++) {
                    uint32_t adr = Kbase +
                        ((np * 16 + (l3 & 1) * 8 + l7) * 72 +
                         g4 * 16 + (l3 >> 1) * 8) * 2;
                    uint32_t r0, r1, r2, r3;
                    ldsm_x4(r0, r1, r2, r3, adr);
                    uint32_t b0[2] = {r0, r2};
                    uint32_t b1[2] = {r1, r3};
                    mma_f16(sc[0][0], qf[0][g4], b0);
                    mma_f16(sc[0][1], qf[0][g4], b1);
                    mma_f16(sc[1][0], qf[1][g4], b0);
                    mma_f16(sc[1][1], qf[1][g4], b1);
                }

                uint32_t pf[2][4];
#pragma unroll
                for (int mi = 0; mi < 2; mi++) {
                    pf[mi][0] = ex2_h2(pack_f16(sc[mi][0][0], sc[mi][0][1]));
                    pf[mi][1] = ex2_h2(pack_f16(sc[mi][0][2], sc[mi][0][3]));
                    pf[mi][2] = ex2_h2(pack_f16(sc[mi][1][0], sc[mi][1][1]));
                    pf[mi][3] = ex2_h2(pack_f16(sc[mi][1][2], sc[mi][1][3]));
                }

                // PV chunk t = np
#pragma unroll
                for (int a = 0; a < 4; a++) {
                    uint32_t adr = Vbase +
                        (16 * np + (l3 & 1) * 8 + l7) * 144 +
                        (2 * a + (l3 >> 1)) * 16;
                    uint32_t v0, v1, v2, v3;
                    ldsm_x4_t(v0, v1, v2, v3, adr);
                    uint32_t bv0[2] = {v0, v1};
                    uint32_t bv1[2] = {v2, v3};
                    mma_f16(o[0][2 * a],     pf[0], bv0);
                    mma_f16(o[0][2 * a + 1], pf[0], bv1);
                    mma_f16(o[1][2 * a],     pf[1], bv0);
                    mma_f16(o[1][2 * a + 1], pf[1], bv1);
                }
                {
                    uint32_t bv[2] = {bones, bones};
                    mma_f16(o[0][8], pf[0], bv);
                    mma_f16(o[1][8], pf[1], bv);
                }
            }
        }

        __syncthreads();
        if (it + 2 < nkt) load_kv(st, (it + 2) * 128);
        else cp_commit();
    }

    // normalize + write fp16 (row sums in tig==0 lanes of o[mi][8])
    int base = lane & 28;
#pragma unroll
    for (int mi = 0; mi < 2; mi++)
#pragma unroll
        for (int hh = 0; hh < 2; hh++) {
            float lsv = __shfl_sync(0xffffffffu, o[mi][8][hh ? 2 : 0], base);
            float inv = 1.f / lsv;
            int row = q0 + wq + mi * 16 + gid + 8 * hh;
#pragma unroll
            for (int n = 0; n < 8; n++) {
                int col = h * CDH + n * 8 + 2 * tig;
                *(uint32_t*)&out[((size_t)b * CS + row) * CD + col] =
                    pack_f16(o[mi][n][2 * hh] * inv, o[mi][n][2 * hh + 1] * inv);
            }
        }
}

// ---------------------------------------------------------------------------
// Fused residual add + LayerNorm
// ---------------------------------------------------------------------------
__global__ __launch_bounds__(256)
void add_ln(const float* __restrict__ chunk, const float* __restrict__ proj,
            const float* __restrict__ g, const float* __restrict__ beta,
            float* __restrict__ out) {
    int row = blockIdx.x;
    int tid = threadIdx.x;
    size_t base = (size_t)row * CD + tid * 4;

    float4 c = *(const float4*)&chunk[base];
    float4 p = *(const float4*)&proj[base];
    float4 x = make_float4(c.x + p.x, c.y + p.y, c.z + p.z, c.w + p.w);

    float s  = x.x + x.y + x.z + x.w;
    float s2 = x.x * x.x + x.y * x.y + x.z * x.z + x.w * x.w;
#pragma unroll
    for (int off = 16; off; off >>= 1) {
        s  += __shfl_xor_sync(0xffffffffu, s,  off);
        s2 += __shfl_xor_sync(0xffffffffu, s2, off);
    }
    __shared__ float rs[8], rs2[8];
    __shared__ float s_mu, s_rstd;
    int lane = tid & 31, warp = tid >> 5;
    if (lane == 0) { rs[warp] = s; rs2[warp] = s2; }
    __syncthreads();
    if (tid == 0) {
        float a = 0.f, b2 = 0.f;
#pragma unroll
        for (int w = 0; w < 8; w++) { a += rs[w]; b2 += rs2[w]; }
        float mean = a * (1.f / CD);
        float var  = b2 * (1.f / CD) - mean * mean;
        s_mu = mean;
        s_rstd = rsqrtf(var + LN_EPS);
    }
    __syncthreads();
    float mu = s_mu, rstd = s_rstd;

    float4 gv = *(const float4*)&g[tid * 4];
    float4 bv = *(const float4*)&beta[tid * 4];
    float4 y;
    y.x = (x.x - mu) * rstd * gv.x + bv.x;
    y.y = (x.y - mu) * rstd * gv.y + bv.y;
    y.z = (x.z - mu) * rstd * gv.z + bv.z;
    y.w = (x.w - mu) * rstd * gv.w + bv.w;
    *(float4*)&out[base] = y;
}

// ---------------------------------------------------------------------------
extern "C" void kernel_launch(void* const* d_in, const int* in_sizes, int n_in,
                              void* d_out, int out_size) {
    const float* emb     = (const float*)d_in[0];
    const float* chunk_w = (const float*)d_in[1];
    const float* chunk_b = (const float*)d_in[2];
    const float* in_w    = (const float*)d_in[3];
    const float* in_b    = (const float*)d_in[4];
    const float* out_w   = (const float*)d_in[5];
    const float* out_b   = (const float*)d_in[6];
    const float* ln_g    = (const float*)d_in[7];
    const float* ln_b    = (const float*)d_in[8];
    float* out = (float*)d_out;

    float *chunk, *proj;
    __half *emb_h, *chunk_h, *qkv_h, *attn_h, *cw_h, *iw_h, *ow_h;
    cudaGetSymbolAddress((void**)&chunk,   g_chunk);
    cudaGetSymbolAddress((void**)&proj,    g_proj);
    cudaGetSymbolAddress((void**)&emb_h,   g_emb_h);
    cudaGetSymbolAddress((void**)&chunk_h, g_chunk_h);
    cudaGetSymbolAddress((void**)&qkv_h,   g_qkv_h);
    cudaGetSymbolAddress((void**)&attn_h,  g_attn_h);
    cudaGetSymbolAddress((void**)&cw_h,    g_cw_h);
    cudaGetSymbolAddress((void**)&iw_h,    g_iw_h);
    cudaGetSymbolAddress((void**)&ow_h,    g_ow_h);

    cudaFuncSetAttribute(gemm_f16<true>,
                         cudaFuncAttributeMaxDynamicSharedMemorySize, GH_SMEM);
    cudaFuncSetAttribute(gemm_f16<false>,
                         cudaFuncAttributeMaxDynamicSharedMemorySize, GH_SMEM);
    cudaFuncSetAttribute(flash_f16,
                         cudaFuncAttributeMaxDynamicSharedMemorySize, FA_SMEM);

    const float qscale = 1.4426950408889634f * 0.125f;   // log2e / sqrt(dh)

    // 0) fused f32 -> f16 conversions
    {
        int n0 = MROWS * CD / 8;
        int n1 = CD * 2 * CD / 8;
        int n2 = 3 * CD * CD / 8;
        int n3 = CD * CD / 8;
        int nt = n0 + n1 + n2 + n3;
        f2h4<<<(nt + 255) / 256, 256>>>(emb, emb_h, n0, chunk_w, cw_h, n1,
                                        in_w, iw_h, n2, out_w, ow_h, n3);
    }
    // 1) chunk = windows @ chunk_w^T + chunk_b  (f32 + f16 outputs)
    {
        dim3 grid(CD / 128, MROWS / 128);
        gemm_f16<true><<<grid, 128, GH_SMEM>>>(emb_h, cw_h, chunk_b,
                                               chunk, chunk_h,
                                               MROWS, CD, 2 * CD, 0, 1.f);
    }
    // 2) qkv = chunk @ in_proj_w^T + in_proj_b  (f16 out; q-cols pre-scaled)
    {
        dim3 grid(3 * CD / 128, MROWS / 128);
        gemm_f16<false><<<grid, 128, GH_SMEM>>>(chunk_h, iw_h, in_b,
                                                nullptr, qkv_h,
                                                MROWS, 3 * CD, CD, CD, qscale);
    }
    // 3) flash attention (fp16 in/out, 128-row q tiles, 128 thr, 3 CTAs/SM)
    {
        dim3 grid(CS / 128, CB * CH);
        flash_f16<<<grid, 128, FA_SMEM>>>(qkv_h, attn_h);
    }
    // 4) proj = attn @ out_proj_w^T + out_proj_b  (f32 output only)
    {
        dim3 grid(CD / 128, MROWS / 128);
        gemm_f16<false><<<grid, 128, GH_SMEM>>>(attn_h, ow_h, out_b,
                                                proj, nullptr,
                                                MROWS, CD, CD, 0, 1.f);
    }
    // 5) out = LayerNorm(chunk + proj)
    add_ln<<<MROWS, 256>>>(chunk, proj, ln_g, ln_b, out);
}